// round 3
// baseline (speedup 1.0000x reference)
#include <cuda_runtime.h>
#include <cuda_fp16.h>

// kendallloss: 1 - 2 * [sum_{i>j} clip(p_i-p_j)*clip(t_i-t_j)] / (N*(N-1))
//
// Strategy: f16x2 packed SIMT over the lower tile-triangle.
//   - 256x256 tiles; block (bi,bj) with bj<=bi; off-diagonal tiles weighted x2,
//     diagonal tiles computed fully (diag pairs contribute 0) weighted x1.
//   - Per 2 pairs: HADD2 + 2xHMNMX2 (pd), HADD2 + 2xHMNMX2 (td), HFMA2 (acc).
//   - fp16x2 accumulator over 16 j-steps (|acc| <= 16, RTN ~unbiased), flushed
//     to fp32 per tile; deterministic block + final reduction in double.

#define MAXN 32768
#define TILE 256
#define RI   8

__device__ __half  g_hp[MAXN];
__device__ __half  g_hnp[MAXN];
__device__ __half  g_ht[MAXN];
__device__ __half  g_hnt[MAXN];
__device__ double  g_part[(MAXN / TILE) * (MAXN / TILE + 1) / 2];

__global__ void prep_kernel(const float* __restrict__ p,
                            const float* __restrict__ t, int n) {
    int i = blockIdx.x * blockDim.x + threadIdx.x;
    if (i < n) {
        float pv = p[i], tv = t[i];
        g_hp[i]  = __float2half(pv);
        g_hnp[i] = __float2half(-pv);
        g_ht[i]  = __float2half(tv);
        g_hnt[i] = __float2half(-tv);
    }
}

__global__ __launch_bounds__(256) void pair_kernel() {
    const int b = blockIdx.x;
    // Decode lower-triangle tile index: b -> (bi, bj), bj <= bi.
    int r = (int)((sqrtf(8.0f * (float)b + 1.0f) - 1.0f) * 0.5f);
    while ((r + 1) * (r + 2) / 2 <= b) r++;
    while (r * (r + 1) / 2 > b) r--;
    const int bi = r;
    const int bj = b - r * (r + 1) / 2;

    const int t = threadIdx.x;
    const int ibase = bi * TILE;
    const int jbase = bj * TILE;

    // Stage the j-side tile: 128 j-pairs, each 8B {(-p[2j],-p[2j+1]), (-t...)}
    __shared__ uint2 sj[TILE / 2];
    if (t < TILE / 2) {
        const unsigned int* np32 = (const unsigned int*)g_hnp;
        const unsigned int* nt32 = (const unsigned int*)g_hnt;
        sj[t] = make_uint2(np32[(jbase >> 1) + t], nt32[(jbase >> 1) + t]);
    }
    __syncthreads();

    // Warp w handles j-steps [w*16, w*16+16); lane handles i-group = lane.
    const int ig = t & 31;
    const int jg = t >> 5;
    const int i0 = ibase + ig * RI;
    const int s0 = jg * 16;

    __half2 hpi[RI], hti[RI], acc[RI];
#pragma unroll
    for (int q = 0; q < RI; q++) {
        hpi[q] = __half2half2(g_hp[i0 + q]);
        hti[q] = __half2half2(g_ht[i0 + q]);
        acc[q] = __float2half2_rn(0.0f);
    }
    const __half2 one2  = __float2half2_rn(1.0f);
    const __half2 mone2 = __float2half2_rn(-1.0f);

#pragma unroll
    for (int s = 0; s < 16; s++) {
        uint2 v = sj[s0 + s];              // broadcast within warp (no conflicts)
        __half2 np2 = *(__half2*)&v.x;
        __half2 nt2 = *(__half2*)&v.y;
#pragma unroll
        for (int q = 0; q < RI; q++) {
            __half2 pd = __hadd2(hpi[q], np2);   // p_i - p_j (x2 pairs)
            pd = __hmin2(pd, one2);
            pd = __hmax2(pd, mone2);
            __half2 td = __hadd2(hti[q], nt2);   // t_i - t_j
            td = __hmin2(td, one2);
            td = __hmax2(td, mone2);
            acc[q] = __hfma2(pd, td, acc[q]);    // fp16x2 partial (<=16 terms)
        }
    }

    // Flush to fp32
    float fa = 0.0f;
#pragma unroll
    for (int q = 0; q < RI; q++) {
        float2 f = __half22float2(acc[q]);
        fa += f.x + f.y;
    }

    // Deterministic block reduction
#pragma unroll
    for (int off = 16; off; off >>= 1)
        fa += __shfl_down_sync(0xffffffffu, fa, off);
    __shared__ float wsum[8];
    if ((t & 31) == 0) wsum[t >> 5] = fa;
    __syncthreads();
    if (t == 0) {
        float bs = 0.0f;
#pragma unroll
        for (int w = 0; w < 8; w++) bs += wsum[w];
        double wgt = (bi == bj) ? 1.0 : 2.0;   // off-diag tiles stand for both orientations
        g_part[b] = wgt * (double)bs;
    }
}

__global__ void final_kernel(float* __restrict__ out, int nblocks, int n) {
    __shared__ double sd[256];
    int t = threadIdx.x;
    double s = 0.0;
    for (int k = t; k < nblocks; k += 256) s += g_part[k];
    sd[t] = s;
    __syncthreads();
    for (int off = 128; off; off >>= 1) {
        if (t < off) sd[t] += sd[t + off];
        __syncthreads();
    }
    if (t == 0) {
        // g_part sums the FULL symmetric matrix; num = full_sum/2,
        // result = 1 - 2*num/denom = 1 - full_sum/denom.
        double denom = (double)n * (double)(n - 1);
        out[0] = (float)(1.0 - sd[0] / denom);
    }
}

extern "C" void kernel_launch(void* const* d_in, const int* in_sizes, int n_in,
                              void* d_out, int out_size) {
    const float* p = (const float*)d_in[0];
    const float* t = (const float*)d_in[1];
    int n = in_sizes[0];   // 16384: divisible by TILE

    prep_kernel<<<(n + 255) / 256, 256>>>(p, t, n);

    int T  = n / TILE;
    int nb = T * (T + 1) / 2;
    pair_kernel<<<nb, 256>>>();

    final_kernel<<<1, 256>>>((float*)d_out, nb, n);
}

// round 4
// speedup vs baseline: 1.3015x; 1.3015x over previous
#include <cuda_runtime.h>
#include <cuda_fp16.h>

// kendallloss: 1 - 2 * [sum_{i>j} clip(p_i-p_j)*clip(t_i-t_j)] / (N*(N-1))
//
// Single-kernel f16x2 sat-trick formulation:
//   pd' = sat(0.5*p_i + (0.5 - 0.5*p_j))  == (clip(p_i-p_j)+1)/2   (ONE HADD2.SAT)
//   q   = (2pd'-1)(2td'-1) = 4*pd'*td' - 2*(pd'+td') + 1           (orientation-symmetric)
// Inner loop = 5 half2 ops per 2 pairs (was 7): HADD2.SAT x2, HFMA2, HADD2 x2.
// Triangle tiling 256x256, off-diag tiles weight 2, diag tiles weight 1.
// Per-thread combine 4P-2S+count in fp32; deterministic block reduce;
// last block (atomic ticket) does the fixed-order double reduction -> out.

#define MAXN 32768
#define TILE 256
#define RI   8

__device__ double       g_part[(MAXN / TILE) * (MAXN / TILE + 1) / 2];
__device__ unsigned int g_done = 0;

__global__ __launch_bounds__(256) void pair_kernel(const float* __restrict__ p,
                                                   const float* __restrict__ tg,
                                                   float* __restrict__ out,
                                                   int n, int nblocks) {
    const int b = blockIdx.x;
    // Decode lower-triangle tile index: b -> (bi, bj), bj <= bi.
    int r = (int)((sqrtf(8.0f * (float)b + 1.0f) - 1.0f) * 0.5f);
    while ((r + 1) * (r + 2) / 2 <= b) r++;
    while (r * (r + 1) / 2 > b) r--;
    const int bi = r;
    const int bj = b - r * (r + 1) / 2;

    const int t = threadIdx.x;
    const int ibase = bi * TILE;
    const int jbase = bj * TILE;

    // Stage j-side tile: 128 half2 pairs of {b_p, b_t} where b = 0.5 - 0.5*x[j].
    __shared__ uint2 sj[TILE / 2];
    if (t < TILE / 2) {
        float2 pv = *(const float2*)(p  + jbase + 2 * t);
        float2 tv = *(const float2*)(tg + jbase + 2 * t);
        __half2 bp = __floats2half2_rn(0.5f - 0.5f * pv.x, 0.5f - 0.5f * pv.y);
        __half2 bt = __floats2half2_rn(0.5f - 0.5f * tv.x, 0.5f - 0.5f * tv.y);
        uint2 u;
        u.x = *(unsigned int*)&bp;
        u.y = *(unsigned int*)&bt;
        sj[t] = u;
    }

    // i-side registers: a = 0.5*x[i], broadcast into both half2 lanes.
    const int ig = t & 31;
    const int jg = t >> 5;
    const int i0 = ibase + ig * RI;
    const int s0 = jg * 16;

    float4 pf0 = *(const float4*)(p  + i0);
    float4 pf1 = *(const float4*)(p  + i0 + 4);
    float4 tf0 = *(const float4*)(tg + i0);
    float4 tf1 = *(const float4*)(tg + i0 + 4);

    __half2 ap[RI], at[RI], accP[RI], accS[RI];
    {
        float pv[RI] = {pf0.x, pf0.y, pf0.z, pf0.w, pf1.x, pf1.y, pf1.z, pf1.w};
        float tv[RI] = {tf0.x, tf0.y, tf0.z, tf0.w, tf1.x, tf1.y, tf1.z, tf1.w};
#pragma unroll
        for (int q = 0; q < RI; q++) {
            ap[q] = __half2half2(__float2half_rn(0.5f * pv[q]));
            at[q] = __half2half2(__float2half_rn(0.5f * tv[q]));
            accP[q] = __float2half2_rn(0.0f);
            accS[q] = __float2half2_rn(0.0f);
        }
    }
    __syncthreads();

#pragma unroll
    for (int s = 0; s < 16; s++) {
        uint2 v = sj[s0 + s];            // warp-uniform broadcast (no conflicts)
        __half2 bp2 = *(__half2*)&v.x;
        __half2 bt2 = *(__half2*)&v.y;
#pragma unroll
        for (int q = 0; q < RI; q++) {
            __half2 pd = __hadd2_sat(ap[q], bp2);     // (clip(p_i-p_j)+1)/2
            __half2 td = __hadd2_sat(at[q], bt2);     // (clip(t_i-t_j)+1)/2
            accP[q] = __hfma2(pd, td, accP[q]);
            __half2 sm = __hadd2(pd, td);
            accS[q] = __hadd2(accS[q], sm);
        }
    }

    // Per-thread combine in fp32: q_sum = 4P - 2S + count (count = 256 pairs/thread)
    float faP = 0.0f, faS = 0.0f;
#pragma unroll
    for (int q = 0; q < RI; q++) {
        float2 fp2 = __half22float2(accP[q]);
        float2 fs2 = __half22float2(accS[q]);
        faP += fp2.x + fp2.y;
        faS += fs2.x + fs2.y;
    }
    float qth = 4.0f * faP - 2.0f * faS + 256.0f;

    // Deterministic block reduction
#pragma unroll
    for (int off = 16; off; off >>= 1)
        qth += __shfl_down_sync(0xffffffffu, qth, off);
    __shared__ float wsum[8];
    if ((t & 31) == 0) wsum[t >> 5] = qth;
    __syncthreads();

    __shared__ int s_last;
    if (t == 0) {
        float bs = 0.0f;
#pragma unroll
        for (int w = 0; w < 8; w++) bs += wsum[w];
        double wgt = (bi == bj) ? 1.0 : 2.0;   // off-diag tile covers both orientations
        g_part[b] = wgt * (double)bs;
        __threadfence();
        unsigned int done = atomicAdd(&g_done, 1u);
        s_last = (done == (unsigned int)(nblocks - 1));
    }
    __syncthreads();

    if (s_last) {
        // Last block: fixed-order double reduction over all tile partials.
        __shared__ double sd[256];
        double s = 0.0;
        for (int k = t; k < nblocks; k += 256) s += g_part[k];
        sd[t] = s;
        __syncthreads();
        for (int off = 128; off; off >>= 1) {
            if (t < off) sd[t] += sd[t + off];
            __syncthreads();
        }
        if (t == 0) {
            double denom = (double)n * (double)(n - 1);
            out[0] = (float)(1.0 - sd[0] / denom);   // 1 - full_sum/denom
            g_done = 0;                               // reset for next graph replay
        }
    }
}

extern "C" void kernel_launch(void* const* d_in, const int* in_sizes, int n_in,
                              void* d_out, int out_size) {
    const float* p = (const float*)d_in[0];
    const float* t = (const float*)d_in[1];
    int n = in_sizes[0];              // 16384, divisible by TILE

    int T  = n / TILE;
    int nb = T * (T + 1) / 2;         // 2080 lower-triangle tiles
    pair_kernel<<<nb, 256>>>(p, t, (float*)d_out, n, nb);
}